// round 2
// baseline (speedup 1.0000x reference)
#include <cuda_runtime.h>

#define NB 2048
#define NN 20000
#define ND 64
#define NDY 32
#define NL 100
#define FETA 0.01f
#define NS1 9          // pass1 N-splits -> 32*9 = 288 blocks (~1 wave @2/SM)
#define NS2 5          // pass2 N-splits -> 32*5 = 160 blocks per branch
#define CHT 313        // ceil(20000/64)
#define CHP1 35        // ceil(313/9)
#define CHP2 63        // ceil(313/5)

// ---------------- scratch (device globals; no allocation allowed) ----------------
__device__ __align__(16) float g_pacc1[NS1 * NB * ND];
__device__ __align__(16) float g_pacc2[NS1 * NB * ND];
__device__ __align__(16) float g_psum[NS1 * NB];
__device__ int g_match[NB];
__device__ __align__(16) float g_xt1[NB * ND];
__device__ __align__(16) float g_xt2[NB * ND];
__device__ int g_yidx1[NB];
__device__ int g_yidx2[NB];
__device__ __align__(16) float g_pnum[2 * NS2 * NB * NDY];
__device__ __align__(16) float g_pden[2 * NS2 * NB];

// Load up to 64 rows x 64 floats from row-major src into smem with row stride 68
// (conflict-free LDS.128 later), zero-padding missing rows. Optionally computes
// per-row sum of squares via 16-lane shuffle reduce.
__device__ __forceinline__ void load64(float* dst, float* sq, const float* src,
                                       int rows, int tid) {
    const float4* s4 = (const float4*)src;
#pragma unroll
    for (int it = 0; it < 4; ++it) {
        int f = tid + it * 256;      // float4 index 0..1023
        int r = f >> 4;              // row 0..63
        int kq = f & 15;             // float4-within-row
        float4 v = make_float4(0.f, 0.f, 0.f, 0.f);
        if (r < rows) v = s4[r * 16 + kq];
        *(float4*)(dst + r * 68 + kq * 4) = v;
        if (sq) {
            float p = v.x * v.x + v.y * v.y + v.z * v.z + v.w * v.w;
            p += __shfl_xor_sync(0xffffffffu, p, 1);
            p += __shfl_xor_sync(0xffffffffu, p, 2);
            p += __shfl_xor_sync(0xffffffffu, p, 4);
            p += __shfl_xor_sync(0xffffffffu, p, 8);
            if (kq == 0) sq[r] = p;
        }
    }
}

__global__ void k_init() {
    int i = blockIdx.x * 256 + threadIdx.x;
    if (i < NB) g_match[i] = NN;   // sentinel: no match
}

// ---------------- Pass 1: e_star GEMM fused with feats^T @ e_star -----------------
// grid (B/64, NS1), 256 threads. smem: Xs,Ss,F1s,F2s (68-stride) + Es[64][64] + norms
__global__ void __launch_bounds__(256, 2)
k_pass1(const float* __restrict__ x, const float* __restrict__ sf,
        const float* __restrict__ f1, const float* __restrict__ f2) {
    extern __shared__ float sm[];
    float* Xs  = sm;                // 4352
    float* Ss  = Xs + 4352;         // 4352
    float* F1s = Ss + 4352;         // 4352
    float* F2s = F1s + 4352;        // 4352
    float* Es  = F2s + 4352;        // 4096
    float* xsq = Es + 4096;         // 64
    float* ssq = xsq + 64;          // 64

    int tid = threadIdx.x;
    int bbase = blockIdx.x * 64;
    int split = blockIdx.y;
    int c0 = split * CHP1;
    int c1 = min(c0 + CHP1, CHT);

    load64(Xs, xsq, x + (size_t)bbase * ND, 64, tid);

    int txa = tid & 15, tya = tid >> 4;   // phase A: b = txa+16i, n = tya+16j
    int txb = tid & 15, tyb = tid >> 4;   // phase B: b = txb*4+i, d = tyb*4+j

    float acc1[4][4] = {}, acc2[4][4] = {}, se[4] = {};

    for (int c = c0; c < c1; ++c) {
        int n0 = c * 64;
        int cnt = min(64, NN - n0);
        __syncthreads();   // protect previous phase-B reads
        load64(Ss, ssq, sf + (size_t)n0 * ND, cnt, tid);
        load64(F1s, 0, f1 + (size_t)n0 * ND, cnt, tid);
        load64(F2s, 0, f2 + (size_t)n0 * ND, cnt, tid);
        __syncthreads();

        // ---- phase A: dot(x_b, star_n) ----
        float dot[4][4] = {};
#pragma unroll 4
        for (int k = 0; k < 64; k += 4) {
            float4 xv[4], sv[4];
#pragma unroll
            for (int i = 0; i < 4; ++i) xv[i] = *(float4*)(Xs + (txa + 16 * i) * 68 + k);
#pragma unroll
            for (int j = 0; j < 4; ++j) sv[j] = *(float4*)(Ss + (tya + 16 * j) * 68 + k);
#pragma unroll
            for (int j = 0; j < 4; ++j)
#pragma unroll
                for (int i = 0; i < 4; ++i)
                    dot[j][i] += sv[j].x * xv[i].x + sv[j].y * xv[i].y +
                                 sv[j].z * xv[i].z + sv[j].w * xv[i].w;
        }
#pragma unroll
        for (int j = 0; j < 4; ++j) {
            int nl = tya + 16 * j, ng = n0 + nl;
            float sq = ssq[nl];
#pragma unroll
            for (int i = 0; i < 4; ++i) {
                int bl = txa + 16 * i;
                float d = fmaxf(xsq[bl] + sq - 2.f * dot[j][i], 0.f);
                float ev = 0.f;
                if (ng < NN) {
                    if (d <= 0.f) atomicMin(&g_match[bbase + bl], ng);
                    ev = __expf(-d);
                }
                Es[nl * 64 + bl] = ev;
            }
        }
        __syncthreads();

        // ---- phase B: acc_k[b,d] += e[n,b] * F_k[n,d]; se[b] += e[n,b] ----
#pragma unroll 4
        for (int n = 0; n < 64; ++n) {
            float4 er = *(float4*)(Es + n * 64 + txb * 4);
            float4 av = *(float4*)(F1s + n * 68 + tyb * 4);
            float4 bv = *(float4*)(F2s + n * 68 + tyb * 4);
            float er4[4] = {er.x, er.y, er.z, er.w};
            float a4[4]  = {av.x, av.y, av.z, av.w};
            float b4[4]  = {bv.x, bv.y, bv.z, bv.w};
#pragma unroll
            for (int i = 0; i < 4; ++i) {
#pragma unroll
                for (int j = 0; j < 4; ++j) {
                    acc1[i][j] += er4[i] * a4[j];
                    acc2[i][j] += er4[i] * b4[j];
                }
            }
            if (tyb == 0) {
#pragma unroll
                for (int i = 0; i < 4; ++i) se[i] += er4[i];
            }
        }
    }

    size_t ob = ((size_t)split * NB + bbase) * ND;
#pragma unroll
    for (int i = 0; i < 4; ++i) {
        *(float4*)&g_pacc1[ob + (txb * 4 + i) * ND + tyb * 4] =
            make_float4(acc1[i][0], acc1[i][1], acc1[i][2], acc1[i][3]);
        *(float4*)&g_pacc2[ob + (txb * 4 + i) * ND + tyb * 4] =
            make_float4(acc2[i][0], acc2[i][1], acc2[i][2], acc2[i][3]);
    }
    if (tyb == 0) {
#pragma unroll
        for (int i = 0; i < 4; ++i)
            g_psum[split * NB + bbase + txb * 4 + i] = se[i];
    }
}

// ---------------- Middle: reduce partials, select xt, y = xt@W+b, argmin ----------
__global__ void __launch_bounds__(256)
k_mid(const float* __restrict__ f1, const float* __restrict__ f2,
      const float* __restrict__ W1, const float* __restrict__ b1,
      const float* __restrict__ W2, const float* __restrict__ b2,
      const float* __restrict__ u1, const float* __restrict__ u2) {
    __shared__ float xts[8][64];
    int warp = threadIdx.x >> 5, lane = threadIdx.x & 31;
    int b = blockIdx.x * 8 + warp;
    if (b >= NB) return;

    float s = 0.f;
#pragma unroll
    for (int t = 0; t < NS1; ++t) s += g_psum[t * NB + b];
    int mi = g_match[b];

    for (int br = 0; br < 2; ++br) {
        const float* pa = br ? g_pacc2 : g_pacc1;
        const float* fs = br ? f2 : f1;
        const float* W  = br ? W2 : W1;
        const float* bb = br ? b2 : b1;
        const float* uu = br ? u2 : u1;
        float* gx = br ? g_xt2 : g_xt1;

        float xa = 0.f, xb2 = 0.f;
        int d0 = lane, d1 = lane + 32;
#pragma unroll
        for (int t = 0; t < NS1; ++t) {
            xa  += pa[(size_t)t * NB * ND + b * ND + d0];
            xb2 += pa[(size_t)t * NB * ND + b * ND + d1];
        }
        xa /= s; xb2 /= s;
        if (mi < NN) {
            xa  = fs[(size_t)mi * ND + d0];
            xb2 = fs[(size_t)mi * ND + d1];
        }
        gx[b * ND + d0] = xa;
        gx[b * ND + d1] = xb2;
        xts[warp][d0] = xa;
        xts[warp][d1] = xb2;
        __syncwarp();

        float y = bb[lane];
#pragma unroll
        for (int d = 0; d < 64; ++d) y += xts[warp][d] * W[d * NDY + lane];

        float best = 3.4e38f;
        int bi = 0;
        for (int l = 0; l < NL; ++l) {
            float diff = y - uu[l * NDY + lane];
            float p = diff * diff;
            p += __shfl_xor_sync(0xffffffffu, p, 16);
            p += __shfl_xor_sync(0xffffffffu, p, 8);
            p += __shfl_xor_sync(0xffffffffu, p, 4);
            p += __shfl_xor_sync(0xffffffffu, p, 2);
            p += __shfl_xor_sync(0xffffffffu, p, 1);
            if (p < best) { best = p; bi = l; }
        }
        if (lane == 0) (br ? g_yidx2 : g_yidx1)[b] = bi;
        __syncwarp();
    }
}

// ---------------- Pass 2: e2 GEMM fused with star_labels^T @ e2 -------------------
// grid (B/64, NS2), launched once per branch.
__global__ void __launch_bounds__(256, 2)
k_pass2(const float* __restrict__ feats, const float* __restrict__ sl,
        const int* __restrict__ lidx, const float* __restrict__ ldist, int br) {
    extern __shared__ float sm[];
    float* Qs  = sm;                // 4352
    float* Ks  = Qs + 4352;         // 4352
    float* Es  = Ks + 4352;         // 4096
    float* Vs  = Es + 4096;         // 2048
    float* Gt  = Vs + 2048;         // 6400
    float* qsq = Gt + 6400;         // 64
    float* ksq = qsq + 64;          // 64
    int* lis = (int*)(ksq + 64);    // 64
    int* yb  = lis + 64;            // 64

    int tid = threadIdx.x;
    int bbase = blockIdx.x * 64;
    int split = blockIdx.y;
    const float* xt = br ? g_xt2 : g_xt1;
    const int* yi = br ? g_yidx2 : g_yidx1;

    load64(Qs, qsq, xt + (size_t)bbase * ND, 64, tid);
    if (tid < 64) yb[tid] = yi[bbase + tid];
    __syncthreads();
    for (int i = tid; i < NL * 64; i += 256) {
        int l = i >> 6, bl = i & 63;
        Gt[i] = FETA * __ldg(&ldist[l * NL + yb[bl]]);
    }

    int txa = tid & 15, tya = tid >> 4;
    int txb = tid & 15, tyb = tid >> 4;   // b = txb*4+i, dy = tyb*2+j
    float accn[4][2] = {};
    float den[4] = {};

    int c0 = split * CHP2, c1 = min(c0 + CHP2, CHT);
    for (int c = c0; c < c1; ++c) {
        int n0 = c * 64;
        int cnt = min(64, NN - n0);
        __syncthreads();
        load64(Ks, ksq, feats + (size_t)n0 * ND, cnt, tid);
        {   // star_labels chunk [cnt, 32] -> Vs
            const float4* s4 = (const float4*)(sl + (size_t)n0 * NDY);
#pragma unroll
            for (int it = 0; it < 2; ++it) {
                int f = tid + it * 256;
                int r = f >> 3, kq = f & 7;
                float4 v = make_float4(0.f, 0.f, 0.f, 0.f);
                if (r < cnt) v = s4[r * 8 + kq];
                *(float4*)(Vs + r * 32 + kq * 4) = v;
            }
        }
        if (tid < 64) lis[tid] = (n0 + tid < NN) ? lidx[n0 + tid] : 0;
        __syncthreads();

        float dot[4][4] = {};
#pragma unroll 4
        for (int k = 0; k < 64; k += 4) {
            float4 qv[4], kv[4];
#pragma unroll
            for (int i = 0; i < 4; ++i) qv[i] = *(float4*)(Qs + (txa + 16 * i) * 68 + k);
#pragma unroll
            for (int j = 0; j < 4; ++j) kv[j] = *(float4*)(Ks + (tya + 16 * j) * 68 + k);
#pragma unroll
            for (int j = 0; j < 4; ++j)
#pragma unroll
                for (int i = 0; i < 4; ++i)
                    dot[j][i] += kv[j].x * qv[i].x + kv[j].y * qv[i].y +
                                 kv[j].z * qv[i].z + kv[j].w * qv[i].w;
        }
#pragma unroll
        for (int j = 0; j < 4; ++j) {
            int nl = tya + 16 * j, ng = n0 + nl;
            float kq2 = ksq[nl];
            int li = lis[nl];
#pragma unroll
            for (int i = 0; i < 4; ++i) {
                int bl = txa + 16 * i;
                float d = fmaxf(qsq[bl] + kq2 - 2.f * dot[j][i], 0.f);
                float ev = (ng < NN) ? __expf(-(d + Gt[li * 64 + bl])) : 0.f;
                Es[nl * 64 + bl] = ev;
            }
        }
        __syncthreads();

#pragma unroll 4
        for (int n = 0; n < 64; ++n) {
            float4 er = *(float4*)(Es + n * 64 + txb * 4);
            float2 vv = *(float2*)(Vs + n * 32 + tyb * 2);
            float er4[4] = {er.x, er.y, er.z, er.w};
#pragma unroll
            for (int i = 0; i < 4; ++i) {
                accn[i][0] += er4[i] * vv.x;
                accn[i][1] += er4[i] * vv.y;
            }
            if (tyb == 0) {
#pragma unroll
                for (int i = 0; i < 4; ++i) den[i] += er4[i];
            }
        }
    }

    float* pnum = g_pnum + ((size_t)br * NS2 + split) * NB * NDY;
    float* pden = g_pden + ((size_t)br * NS2 + split) * NB;
#pragma unroll
    for (int i = 0; i < 4; ++i)
        *(float2*)&pnum[(bbase + txb * 4 + i) * NDY + tyb * 2] =
            make_float2(accn[i][0], accn[i][1]);
    if (tyb == 0) {
#pragma unroll
        for (int i = 0; i < 4; ++i) pden[bbase + txb * 4 + i] = den[i];
    }
}

__global__ void k_final(float* __restrict__ out) {
    int i = blockIdx.x * 256 + threadIdx.x;
    if (i >= NB * NDY) return;
    int b = i / NDY;
    float n1 = 0.f, n2 = 0.f, d1 = 0.f, d2 = 0.f;
#pragma unroll
    for (int t = 0; t < NS2; ++t) {
        n1 += g_pnum[(size_t)t * NB * NDY + i];
        n2 += g_pnum[((size_t)NS2 + t) * NB * NDY + i];
        d1 += g_pden[t * NB + b];
        d2 += g_pden[(NS2 + t) * NB + b];
    }
    out[i] = 0.5f * (n1 / d1 + n2 / d2);
}

#define SMEM1 ((4352 * 4 + 4096 + 128) * 4)           // 86528 B
#define SMEM2 ((4352 * 2 + 4096 + 2048 + 6400 + 128) * 4 + 128 * 4)  // 86016 B

extern "C" void kernel_launch(void* const* d_in, const int* in_sizes, int n_in,
                              void* d_out, int out_size) {
    const float* x   = (const float*)d_in[0];
    const float* sf  = (const float*)d_in[1];
    const float* sl  = (const float*)d_in[2];
    const float* f1  = (const float*)d_in[3];
    const float* f2  = (const float*)d_in[4];
    const float* u1  = (const float*)d_in[5];
    const float* u2  = (const float*)d_in[6];
    const float* ld1 = (const float*)d_in[7];
    const float* ld2 = (const float*)d_in[8];
    const float* W1  = (const float*)d_in[9];
    const float* b1  = (const float*)d_in[10];
    const float* W2  = (const float*)d_in[11];
    const float* b2  = (const float*)d_in[12];
    const int*   li1 = (const int*)d_in[13];
    const int*   li2 = (const int*)d_in[14];
    float* out = (float*)d_out;

    cudaFuncSetAttribute(k_pass1, cudaFuncAttributeMaxDynamicSharedMemorySize, SMEM1);
    cudaFuncSetAttribute(k_pass2, cudaFuncAttributeMaxDynamicSharedMemorySize, SMEM2);

    k_init<<<8, 256>>>();
    k_pass1<<<dim3(32, NS1), 256, SMEM1>>>(x, sf, f1, f2);
    k_mid<<<256, 256>>>(f1, f2, W1, b1, W2, b2, u1, u2);
    k_pass2<<<dim3(32, NS2), 256, SMEM2>>>(f1, sl, li1, ld1, 0);
    k_pass2<<<dim3(32, NS2), 256, SMEM2>>>(f2, sl, li2, ld2, 1);
    k_final<<<256, 256>>>(out);
}

// round 4
// speedup vs baseline: 1.4114x; 1.4114x over previous
#include <cuda_runtime.h>

#define NB 2048
#define NN 20000
#define ND 64
#define NDY 32
#define NL 100
#define FETA 0.01f
#define NS1 9          // pass1 N-splits -> 32*9 = 288 blocks (~1 wave @2/SM)
#define NS2 9          // pass2 N-splits; x2 branches -> 576 blocks (~2 waves @2/SM)
#define CHT 313        // ceil(20000/64)
#define CHP1 35        // ceil(313/9)
#define CHP2 35        // ceil(313/9)

// ---------------- scratch (device globals; no allocation allowed) ----------------
__device__ __align__(16) float g_pacc1[NS1 * NB * ND];
__device__ __align__(16) float g_pacc2[NS1 * NB * ND];
__device__ __align__(16) float g_psum[NS1 * NB];
__device__ int g_match[NB];
__device__ __align__(16) float g_xt1[NB * ND];
__device__ __align__(16) float g_xt2[NB * ND];
__device__ int g_yidx1[NB];
__device__ int g_yidx2[NB];
__device__ __align__(16) float g_pnum[2 * NS2 * NB * NDY];
__device__ __align__(16) float g_pden[2 * NS2 * NB];

// Load up to 64 rows x 64 floats from row-major src into smem with row stride 68
// (conflict-free LDS.128 later), zero-padding missing rows. Optionally computes
// per-row sum of squares via 16-lane shuffle reduce.
__device__ __forceinline__ void load64(float* dst, float* sq, const float* src,
                                       int rows, int tid) {
    const float4* s4 = (const float4*)src;
#pragma unroll
    for (int it = 0; it < 4; ++it) {
        int f = tid + it * 256;      // float4 index 0..1023
        int r = f >> 4;              // row 0..63
        int kq = f & 15;             // float4-within-row
        float4 v = make_float4(0.f, 0.f, 0.f, 0.f);
        if (r < rows) v = s4[r * 16 + kq];
        *(float4*)(dst + r * 68 + kq * 4) = v;
        if (sq) {
            float p = v.x * v.x + v.y * v.y + v.z * v.z + v.w * v.w;
            p += __shfl_xor_sync(0xffffffffu, p, 1);
            p += __shfl_xor_sync(0xffffffffu, p, 2);
            p += __shfl_xor_sync(0xffffffffu, p, 4);
            p += __shfl_xor_sync(0xffffffffu, p, 8);
            if (kq == 0) sq[r] = p;
        }
    }
}

__global__ void k_init() {
    int i = blockIdx.x * 256 + threadIdx.x;
    if (i < NB) g_match[i] = NN;   // sentinel: no match
}

// ---------------- Pass 1: e_star GEMM fused with feats^T @ e_star -----------------
// grid (B/64, NS1), 256 threads. smem: Xs,Ss,F1s,F2s (68-stride) + Es[64][64] + norms
__global__ void __launch_bounds__(256, 2)
k_pass1(const float* __restrict__ x, const float* __restrict__ sf,
        const float* __restrict__ f1, const float* __restrict__ f2) {
    extern __shared__ float sm[];
    float* Xs  = sm;                // 4352
    float* Ss  = Xs + 4352;         // 4352
    float* F1s = Ss + 4352;         // 4352
    float* F2s = F1s + 4352;        // 4352
    float* Es  = F2s + 4352;        // 4096
    float* xsq = Es + 4096;         // 64
    float* ssq = xsq + 64;          // 64

    int tid = threadIdx.x;
    int bbase = blockIdx.x * 64;
    int split = blockIdx.y;
    int c0 = split * CHP1;
    int c1 = min(c0 + CHP1, CHT);

    load64(Xs, xsq, x + (size_t)bbase * ND, 64, tid);

    int txa = tid & 15, tya = tid >> 4;   // phase A: b = txa+16i, n = tya+16j
    int txb = tid & 15, tyb = tid >> 4;   // phase B: b = txb*4+i, d = tyb*4+j

    float acc1[4][4] = {}, acc2[4][4] = {}, se[4] = {};

    for (int c = c0; c < c1; ++c) {
        int n0 = c * 64;
        int cnt = min(64, NN - n0);
        __syncthreads();   // protect previous phase-B reads
        load64(Ss, ssq, sf + (size_t)n0 * ND, cnt, tid);
        load64(F1s, 0, f1 + (size_t)n0 * ND, cnt, tid);
        load64(F2s, 0, f2 + (size_t)n0 * ND, cnt, tid);
        __syncthreads();

        // ---- phase A: dot(x_b, star_n) ----
        float dot[4][4] = {};
#pragma unroll 4
        for (int k = 0; k < 64; k += 4) {
            float4 xv[4], sv[4];
#pragma unroll
            for (int i = 0; i < 4; ++i) xv[i] = *(float4*)(Xs + (txa + 16 * i) * 68 + k);
#pragma unroll
            for (int j = 0; j < 4; ++j) sv[j] = *(float4*)(Ss + (tya + 16 * j) * 68 + k);
#pragma unroll
            for (int j = 0; j < 4; ++j)
#pragma unroll
                for (int i = 0; i < 4; ++i)
                    dot[j][i] += sv[j].x * xv[i].x + sv[j].y * xv[i].y +
                                 sv[j].z * xv[i].z + sv[j].w * xv[i].w;
        }
#pragma unroll
        for (int j = 0; j < 4; ++j) {
            int nl = tya + 16 * j, ng = n0 + nl;
            float sq = ssq[nl];
#pragma unroll
            for (int i = 0; i < 4; ++i) {
                int bl = txa + 16 * i;
                float d = fmaxf(xsq[bl] + sq - 2.f * dot[j][i], 0.f);
                float ev = 0.f;
                if (ng < NN) {
                    if (d <= 0.f) atomicMin(&g_match[bbase + bl], ng);
                    ev = __expf(-d);
                }
                Es[nl * 64 + bl] = ev;
            }
        }
        __syncthreads();

        // ---- phase B: acc_k[b,d] += e[n,b] * F_k[n,d]; se[b] += e[n,b] ----
#pragma unroll 4
        for (int n = 0; n < 64; ++n) {
            float4 er = *(float4*)(Es + n * 64 + txb * 4);
            float4 av = *(float4*)(F1s + n * 68 + tyb * 4);
            float4 bv = *(float4*)(F2s + n * 68 + tyb * 4);
            float er4[4] = {er.x, er.y, er.z, er.w};
            float a4[4]  = {av.x, av.y, av.z, av.w};
            float b4[4]  = {bv.x, bv.y, bv.z, bv.w};
#pragma unroll
            for (int i = 0; i < 4; ++i) {
#pragma unroll
                for (int j = 0; j < 4; ++j) {
                    acc1[i][j] += er4[i] * a4[j];
                    acc2[i][j] += er4[i] * b4[j];
                }
            }
            if (tyb == 0) {
#pragma unroll
                for (int i = 0; i < 4; ++i) se[i] += er4[i];
            }
        }
    }

    size_t ob = ((size_t)split * NB + bbase) * ND;
#pragma unroll
    for (int i = 0; i < 4; ++i) {
        *(float4*)&g_pacc1[ob + (txb * 4 + i) * ND + tyb * 4] =
            make_float4(acc1[i][0], acc1[i][1], acc1[i][2], acc1[i][3]);
        *(float4*)&g_pacc2[ob + (txb * 4 + i) * ND + tyb * 4] =
            make_float4(acc2[i][0], acc2[i][1], acc2[i][2], acc2[i][3]);
    }
    if (tyb == 0) {
#pragma unroll
        for (int i = 0; i < 4; ++i)
            g_psum[split * NB + bbase + txb * 4 + i] = se[i];
    }
}

// ---------------- Middle: reduce partials, select xt, y = xt@W+b, argmin ----------
__global__ void __launch_bounds__(256)
k_mid(const float* __restrict__ f1, const float* __restrict__ f2,
      const float* __restrict__ W1, const float* __restrict__ b1,
      const float* __restrict__ W2, const float* __restrict__ b2,
      const float* __restrict__ u1, const float* __restrict__ u2) {
    __shared__ float xts[8][64];
    int warp = threadIdx.x >> 5, lane = threadIdx.x & 31;
    int b = blockIdx.x * 8 + warp;
    if (b >= NB) return;

    float s = 0.f;
#pragma unroll
    for (int t = 0; t < NS1; ++t) s += g_psum[t * NB + b];
    int mi = g_match[b];

    for (int br = 0; br < 2; ++br) {
        const float* pa = br ? g_pacc2 : g_pacc1;
        const float* fs = br ? f2 : f1;
        const float* W  = br ? W2 : W1;
        const float* bb = br ? b2 : b1;
        const float* uu = br ? u2 : u1;
        float* gx = br ? g_xt2 : g_xt1;

        float xa = 0.f, xb2 = 0.f;
        int d0 = lane, d1 = lane + 32;
#pragma unroll
        for (int t = 0; t < NS1; ++t) {
            xa  += pa[(size_t)t * NB * ND + b * ND + d0];
            xb2 += pa[(size_t)t * NB * ND + b * ND + d1];
        }
        xa /= s; xb2 /= s;
        if (mi < NN) {
            xa  = fs[(size_t)mi * ND + d0];
            xb2 = fs[(size_t)mi * ND + d1];
        }
        gx[b * ND + d0] = xa;
        gx[b * ND + d1] = xb2;
        xts[warp][d0] = xa;
        xts[warp][d1] = xb2;
        __syncwarp();

        float y = bb[lane];
#pragma unroll
        for (int d = 0; d < 64; ++d) y += xts[warp][d] * W[d * NDY + lane];

        float best = 3.4e38f;
        int bi = 0;
        for (int l = 0; l < NL; ++l) {
            float diff = y - uu[l * NDY + lane];
            float p = diff * diff;
            p += __shfl_xor_sync(0xffffffffu, p, 16);
            p += __shfl_xor_sync(0xffffffffu, p, 8);
            p += __shfl_xor_sync(0xffffffffu, p, 4);
            p += __shfl_xor_sync(0xffffffffu, p, 2);
            p += __shfl_xor_sync(0xffffffffu, p, 1);
            if (p < best) { best = p; bi = l; }
        }
        if (lane == 0) (br ? g_yidx2 : g_yidx1)[b] = bi;
        __syncwarp();
    }
}

// ---------------- Pass 2: e2 GEMM fused with star_labels^T @ e2 -------------------
// grid (B/64, NS2, 2): z selects the branch. Both branches in one launch so the
// block scheduler keeps every SM at 2 resident blocks across ~2 full waves.
__global__ void __launch_bounds__(256, 2)
k_pass2(const float* __restrict__ f1, const float* __restrict__ f2,
        const float* __restrict__ sl,
        const int* __restrict__ li1, const int* __restrict__ li2,
        const float* __restrict__ ld1, const float* __restrict__ ld2) {
    extern __shared__ float sm[];
    float* Qs  = sm;                // 4352
    float* Ks  = Qs + 4352;         // 4352
    float* Es  = Ks + 4352;         // 4096
    float* Vs  = Es + 4096;         // 2048
    float* Gt  = Vs + 2048;         // 6400
    float* qsq = Gt + 6400;         // 64
    float* ksq = qsq + 64;          // 64
    int* lis = (int*)(ksq + 64);    // 64
    int* yb  = lis + 64;            // 64

    int tid = threadIdx.x;
    int bbase = blockIdx.x * 64;
    int split = blockIdx.y;
    int br = blockIdx.z;
    const float* feats = br ? f2 : f1;
    const int* lidx = br ? li2 : li1;
    const float* ldist = br ? ld2 : ld1;
    const float* xt = br ? g_xt2 : g_xt1;
    const int* yi = br ? g_yidx2 : g_yidx1;

    load64(Qs, qsq, xt + (size_t)bbase * ND, 64, tid);
    if (tid < 64) yb[tid] = yi[bbase + tid];
    __syncthreads();
    for (int i = tid; i < NL * 64; i += 256) {
        int l = i >> 6, bl = i & 63;
        Gt[i] = FETA * __ldg(&ldist[l * NL + yb[bl]]);
    }

    int txa = tid & 15, tya = tid >> 4;
    int txb = tid & 15, tyb = tid >> 4;   // b = txb*4+i, dy = tyb*2+j
    float accn[4][2] = {};
    float den[4] = {};

    int c0 = split * CHP2, c1 = min(c0 + CHP2, CHT);
    for (int c = c0; c < c1; ++c) {
        int n0 = c * 64;
        int cnt = min(64, NN - n0);
        __syncthreads();
        load64(Ks, ksq, feats + (size_t)n0 * ND, cnt, tid);
        {   // star_labels chunk [cnt, 32] -> Vs
            const float4* s4 = (const float4*)(sl + (size_t)n0 * NDY);
#pragma unroll
            for (int it = 0; it < 2; ++it) {
                int f = tid + it * 256;
                int r = f >> 3, kq = f & 7;
                float4 v = make_float4(0.f, 0.f, 0.f, 0.f);
                if (r < cnt) v = s4[r * 8 + kq];
                *(float4*)(Vs + r * 32 + kq * 4) = v;
            }
        }
        if (tid < 64) lis[tid] = (n0 + tid < NN) ? lidx[n0 + tid] : 0;
        __syncthreads();

        float dot[4][4] = {};
#pragma unroll 4
        for (int k = 0; k < 64; k += 4) {
            float4 qv[4], kv[4];
#pragma unroll
            for (int i = 0; i < 4; ++i) qv[i] = *(float4*)(Qs + (txa + 16 * i) * 68 + k);
#pragma unroll
            for (int j = 0; j < 4; ++j) kv[j] = *(float4*)(Ks + (tya + 16 * j) * 68 + k);
#pragma unroll
            for (int j = 0; j < 4; ++j)
#pragma unroll
                for (int i = 0; i < 4; ++i)
                    dot[j][i] += kv[j].x * qv[i].x + kv[j].y * qv[i].y +
                                 kv[j].z * qv[i].z + kv[j].w * qv[i].w;
        }
#pragma unroll
        for (int j = 0; j < 4; ++j) {
            int nl = tya + 16 * j, ng = n0 + nl;
            float kq2 = ksq[nl];
            int li = lis[nl];
#pragma unroll
            for (int i = 0; i < 4; ++i) {
                int bl = txa + 16 * i;
                float d = fmaxf(qsq[bl] + kq2 - 2.f * dot[j][i], 0.f);
                float ev = (ng < NN) ? __expf(-(d + Gt[li * 64 + bl])) : 0.f;
                Es[nl * 64 + bl] = ev;
            }
        }
        __syncthreads();

#pragma unroll 4
        for (int n = 0; n < 64; ++n) {
            float4 er = *(float4*)(Es + n * 64 + txb * 4);
            float2 vv = *(float2*)(Vs + n * 32 + tyb * 2);
            float er4[4] = {er.x, er.y, er.z, er.w};
#pragma unroll
            for (int i = 0; i < 4; ++i) {
                accn[i][0] += er4[i] * vv.x;
                accn[i][1] += er4[i] * vv.y;
            }
            if (tyb == 0) {
#pragma unroll
                for (int i = 0; i < 4; ++i) den[i] += er4[i];
            }
        }
    }

    float* pnum = g_pnum + ((size_t)br * NS2 + split) * NB * NDY;
    float* pden = g_pden + ((size_t)br * NS2 + split) * NB;
#pragma unroll
    for (int i = 0; i < 4; ++i)
        *(float2*)&pnum[(bbase + txb * 4 + i) * NDY + tyb * 2] =
            make_float2(accn[i][0], accn[i][1]);
    if (tyb == 0) {
#pragma unroll
        for (int i = 0; i < 4; ++i) pden[bbase + txb * 4 + i] = den[i];
    }
}

__global__ void k_final(float* __restrict__ out) {
    int i = blockIdx.x * 256 + threadIdx.x;
    if (i >= NB * NDY) return;
    int b = i / NDY;
    float n1 = 0.f, n2 = 0.f, d1 = 0.f, d2 = 0.f;
#pragma unroll
    for (int t = 0; t < NS2; ++t) {
        n1 += g_pnum[(size_t)t * NB * NDY + i];
        n2 += g_pnum[((size_t)NS2 + t) * NB * NDY + i];
        d1 += g_pden[t * NB + b];
        d2 += g_pden[(NS2 + t) * NB + b];
    }
    out[i] = 0.5f * (n1 / d1 + n2 / d2);
}

#define SMEM1 ((4352 * 4 + 4096 + 128) * 4)           // 86528 B
#define SMEM2 ((4352 * 2 + 4096 + 2048 + 6400 + 128) * 4 + 128 * 4)  // 86016 B

extern "C" void kernel_launch(void* const* d_in, const int* in_sizes, int n_in,
                              void* d_out, int out_size) {
    const float* x   = (const float*)d_in[0];
    const float* sf  = (const float*)d_in[1];
    const float* sl  = (const float*)d_in[2];
    const float* f1  = (const float*)d_in[3];
    const float* f2  = (const float*)d_in[4];
    const float* u1  = (const float*)d_in[5];
    const float* u2  = (const float*)d_in[6];
    const float* ld1 = (const float*)d_in[7];
    const float* ld2 = (const float*)d_in[8];
    const float* W1  = (const float*)d_in[9];
    const float* b1  = (const float*)d_in[10];
    const float* W2  = (const float*)d_in[11];
    const float* b2  = (const float*)d_in[12];
    const int*   li1 = (const int*)d_in[13];
    const int*   li2 = (const int*)d_in[14];
    float* out = (float*)d_out;

    cudaFuncSetAttribute(k_pass1, cudaFuncAttributeMaxDynamicSharedMemorySize, SMEM1);
    cudaFuncSetAttribute(k_pass2, cudaFuncAttributeMaxDynamicSharedMemorySize, SMEM2);

    k_init<<<8, 256>>>();
    k_pass1<<<dim3(32, NS1), 256, SMEM1>>>(x, sf, f1, f2);
    k_mid<<<256, 256>>>(f1, f2, W1, b1, W2, b2, u1, u2);
    k_pass2<<<dim3(32, NS2, 2), 256, SMEM2>>>(f1, f2, sl, li1, li2, ld1, ld2);
    k_final<<<256, 256>>>(out);
}

// round 5
// speedup vs baseline: 1.8108x; 1.2830x over previous
#include <cuda_runtime.h>
#include <cstdint>

#define NB 2048
#define NN 20000
#define ND 64
#define NDY 32
#define NL 100
#define FETA 0.01f
#define NS1 9          // pass1 N-splits -> 288 blocks (~1 wave @2/SM)
#define NS2 9          // pass2 N-splits; x2 branches -> 576 blocks (~2 waves @2/SM)
#define CHT 313        // ceil(20000/64)
#define CHP1 35
#define CHP2 35
#define MATCH_EPS 1e-3f   // tf32 dot noise ~1e-4; min distinct-row sqdist ~0.05

// ---------------- scratch (device globals; no allocation allowed) ----------------
__device__ __align__(16) float g_pacc1[NS1 * NB * ND];
__device__ __align__(16) float g_pacc2[NS1 * NB * ND];
__device__ __align__(16) float g_psum[NS1 * NB];
__device__ int g_match[NB];
__device__ __align__(16) float g_xt1[NB * ND];
__device__ __align__(16) float g_xt2[NB * ND];
__device__ int g_yidx1[NB];
__device__ int g_yidx2[NB];
__device__ __align__(16) float g_pnum[2 * NS2 * NB * NDY];
__device__ __align__(16) float g_pden[2 * NS2 * NB];

// m16n8k8 tf32 mma: D = A*B + D. A row-major 16x8, B col-major 8x8 (fragments per PTX spec).
__device__ __forceinline__ void mma_tf32(float c[4], uint32_t a0, uint32_t a1,
                                         uint32_t a2, uint32_t a3,
                                         uint32_t b0, uint32_t b1) {
    asm volatile(
        "mma.sync.aligned.m16n8k8.row.col.f32.tf32.tf32.f32 "
        "{%0,%1,%2,%3}, {%4,%5,%6,%7}, {%8,%9}, {%0,%1,%2,%3};\n"
        : "+f"(c[0]), "+f"(c[1]), "+f"(c[2]), "+f"(c[3])
        : "r"(a0), "r"(a1), "r"(a2), "r"(a3), "r"(b0), "r"(b1));
}

// Load up to 64 rows x 64 floats from row-major src into smem with row stride 68
// (conflict-free LDS later), zero-padding missing rows. Optionally computes
// per-row sum of squares via 16-lane shuffle reduce.
__device__ __forceinline__ void load64(float* dst, float* sq, const float* src,
                                       int rows, int tid) {
    const float4* s4 = (const float4*)src;
#pragma unroll
    for (int it = 0; it < 4; ++it) {
        int f = tid + it * 256;      // float4 index 0..1023
        int r = f >> 4;              // row 0..63
        int kq = f & 15;             // float4-within-row
        float4 v = make_float4(0.f, 0.f, 0.f, 0.f);
        if (r < rows) v = s4[r * 16 + kq];
        *(float4*)(dst + r * 68 + kq * 4) = v;
        if (sq) {
            float p = v.x * v.x + v.y * v.y + v.z * v.z + v.w * v.w;
            p += __shfl_xor_sync(0xffffffffu, p, 1);
            p += __shfl_xor_sync(0xffffffffu, p, 2);
            p += __shfl_xor_sync(0xffffffffu, p, 4);
            p += __shfl_xor_sync(0xffffffffu, p, 8);
            if (kq == 0) sq[r] = p;
        }
    }
}

__global__ void k_init() {
    int i = blockIdx.x * 256 + threadIdx.x;
    if (i < NB) g_match[i] = NN;   // sentinel: no match
}

// ---------------- Pass 1: e_star via tf32 mma, fused with feats^T @ e_star --------
__global__ void __launch_bounds__(256, 2)
k_pass1(const float* __restrict__ x, const float* __restrict__ sf,
        const float* __restrict__ f1, const float* __restrict__ f2) {
    extern __shared__ float sm[];
    float* Xs  = sm;                // 4352
    float* Ss  = Xs + 4352;         // 4352
    float* F1s = Ss + 4352;         // 4352
    float* F2s = F1s + 4352;        // 4352
    float* Es  = F2s + 4352;        // 4352 (stride 68)
    float* xsq = Es + 4352;         // 64
    float* ssq = xsq + 64;          // 64

    int tid = threadIdx.x;
    int bbase = blockIdx.x * 64;
    int split = blockIdx.y;
    int c0 = split * CHP1;
    int c1 = min(c0 + CHP1, CHT);

    load64(Xs, xsq, x + (size_t)bbase * ND, 64, tid);

    // mma thread mapping
    int w = tid >> 5, lane = tid & 31;
    int lr = lane >> 2, lc = lane & 3;
    int m0 = (w & 3) * 16;          // n offset (A rows)
    int bq = (w >> 2) * 32;         // b offset (B cols), 4 tiles of 8
    const uint32_t* Su = (const uint32_t*)Ss;
    const uint32_t* Xu = (const uint32_t*)Xs;

    int txb = tid & 15, tyb = tid >> 4;   // phase B: b = txb*4+i, d = tyb*4+j
    float acc1[4][4] = {}, acc2[4][4] = {}, se[4] = {};

    for (int c = c0; c < c1; ++c) {
        int n0 = c * 64;
        int cnt = min(64, NN - n0);
        __syncthreads();   // protect previous phase-B reads
        load64(Ss, ssq, sf + (size_t)n0 * ND, cnt, tid);
        load64(F1s, 0, f1 + (size_t)n0 * ND, cnt, tid);
        load64(F2s, 0, f2 + (size_t)n0 * ND, cnt, tid);
        __syncthreads();

        // ---- phase A: E = exp(-max(|x|^2+|s|^2-2 x.s, 0)) via tf32 mma ----
        float cfr[4][4];
#pragma unroll
        for (int t = 0; t < 4; ++t)
#pragma unroll
            for (int rg = 0; rg < 4; ++rg) cfr[t][rg] = 0.f;
#pragma unroll
        for (int ks = 0; ks < 64; ks += 8) {
            uint32_t a0 = Su[(m0 + lr) * 68 + ks + lc];
            uint32_t a1 = Su[(m0 + 8 + lr) * 68 + ks + lc];
            uint32_t a2 = Su[(m0 + lr) * 68 + ks + 4 + lc];
            uint32_t a3 = Su[(m0 + 8 + lr) * 68 + ks + 4 + lc];
#pragma unroll
            for (int t = 0; t < 4; ++t) {
                int bt = bq + t * 8;
                uint32_t b0 = Xu[(bt + lr) * 68 + ks + lc];
                uint32_t b1 = Xu[(bt + lr) * 68 + ks + 4 + lc];
                mma_tf32(cfr[t], a0, a1, a2, a3, b0, b1);
            }
        }
#pragma unroll
        for (int t = 0; t < 4; ++t) {
            int bt = bq + t * 8;
#pragma unroll
            for (int rg = 0; rg < 4; ++rg) {
                int nl = m0 + lr + ((rg >> 1) ? 8 : 0);
                int bl = bt + 2 * lc + (rg & 1);
                int ng = n0 + nl;
                float d = fmaxf(xsq[bl] + ssq[nl] - 2.f * cfr[t][rg], 0.f);
                float ev = 0.f;
                if (ng < NN) {
                    if (d <= MATCH_EPS) atomicMin(&g_match[bbase + bl], ng);
                    ev = __expf(-d);
                }
                Es[nl * 68 + bl] = ev;
            }
        }
        __syncthreads();

        // ---- phase B: acc_k[b,d] += e[n,b] * F_k[n,d]; se[b] += e[n,b] ----
#pragma unroll 4
        for (int n = 0; n < 64; ++n) {
            float4 er = *(float4*)(Es + n * 68 + txb * 4);
            float4 av = *(float4*)(F1s + n * 68 + tyb * 4);
            float4 bv = *(float4*)(F2s + n * 68 + tyb * 4);
            float er4[4] = {er.x, er.y, er.z, er.w};
            float a4[4]  = {av.x, av.y, av.z, av.w};
            float b4[4]  = {bv.x, bv.y, bv.z, bv.w};
#pragma unroll
            for (int i = 0; i < 4; ++i) {
#pragma unroll
                for (int j = 0; j < 4; ++j) {
                    acc1[i][j] += er4[i] * a4[j];
                    acc2[i][j] += er4[i] * b4[j];
                }
            }
            if (tyb == 0) {
#pragma unroll
                for (int i = 0; i < 4; ++i) se[i] += er4[i];
            }
        }
    }

    size_t ob = ((size_t)split * NB + bbase) * ND;
#pragma unroll
    for (int i = 0; i < 4; ++i) {
        *(float4*)&g_pacc1[ob + (txb * 4 + i) * ND + tyb * 4] =
            make_float4(acc1[i][0], acc1[i][1], acc1[i][2], acc1[i][3]);
        *(float4*)&g_pacc2[ob + (txb * 4 + i) * ND + tyb * 4] =
            make_float4(acc2[i][0], acc2[i][1], acc2[i][2], acc2[i][3]);
    }
    if (tyb == 0) {
#pragma unroll
        for (int i = 0; i < 4; ++i)
            g_psum[split * NB + bbase + txb * 4 + i] = se[i];
    }
}

// ---------------- Middle: reduce partials, select xt, y = xt@W+b, argmin ----------
__global__ void __launch_bounds__(256)
k_mid(const float* __restrict__ f1, const float* __restrict__ f2,
      const float* __restrict__ W1, const float* __restrict__ b1,
      const float* __restrict__ W2, const float* __restrict__ b2,
      const float* __restrict__ u1, const float* __restrict__ u2) {
    __shared__ float xts[8][64];
    int warp = threadIdx.x >> 5, lane = threadIdx.x & 31;
    int b = blockIdx.x * 8 + warp;
    if (b >= NB) return;

    float s = 0.f;
#pragma unroll
    for (int t = 0; t < NS1; ++t) s += g_psum[t * NB + b];
    int mi = g_match[b];

    for (int br = 0; br < 2; ++br) {
        const float* pa = br ? g_pacc2 : g_pacc1;
        const float* fs = br ? f2 : f1;
        const float* W  = br ? W2 : W1;
        const float* bb = br ? b2 : b1;
        const float* uu = br ? u2 : u1;
        float* gx = br ? g_xt2 : g_xt1;

        float xa = 0.f, xb2 = 0.f;
        int d0 = lane, d1 = lane + 32;
#pragma unroll
        for (int t = 0; t < NS1; ++t) {
            xa  += pa[(size_t)t * NB * ND + b * ND + d0];
            xb2 += pa[(size_t)t * NB * ND + b * ND + d1];
        }
        xa /= s; xb2 /= s;
        if (mi < NN) {
            xa  = fs[(size_t)mi * ND + d0];
            xb2 = fs[(size_t)mi * ND + d1];
        }
        gx[b * ND + d0] = xa;
        gx[b * ND + d1] = xb2;
        xts[warp][d0] = xa;
        xts[warp][d1] = xb2;
        __syncwarp();

        float y = bb[lane];
#pragma unroll
        for (int d = 0; d < 64; ++d) y += xts[warp][d] * W[d * NDY + lane];

        float best = 3.4e38f;
        int bi = 0;
        for (int l = 0; l < NL; ++l) {
            float diff = y - uu[l * NDY + lane];
            float p = diff * diff;
            p += __shfl_xor_sync(0xffffffffu, p, 16);
            p += __shfl_xor_sync(0xffffffffu, p, 8);
            p += __shfl_xor_sync(0xffffffffu, p, 4);
            p += __shfl_xor_sync(0xffffffffu, p, 2);
            p += __shfl_xor_sync(0xffffffffu, p, 1);
            if (p < best) { best = p; bi = l; }
        }
        if (lane == 0) (br ? g_yidx2 : g_yidx1)[b] = bi;
        __syncwarp();
    }
}

// ---------------- Pass 2: e2 via tf32 mma, fused with star_labels^T @ e2 ----------
// grid (B/64, NS2, 2): z selects the branch.
__global__ void __launch_bounds__(256, 2)
k_pass2(const float* __restrict__ f1, const float* __restrict__ f2,
        const float* __restrict__ sl,
        const int* __restrict__ li1, const int* __restrict__ li2,
        const float* __restrict__ ld1, const float* __restrict__ ld2) {
    extern __shared__ float sm[];
    float* Qs  = sm;                // 4352
    float* Ks  = Qs + 4352;         // 4352
    float* Es  = Ks + 4352;         // 4352 (stride 68)
    float* Vs  = Es + 4352;         // 2048
    float* Gt  = Vs + 2048;         // 6500 (stride 65)
    float* qsq = Gt + 6500;         // 64
    float* ksq = qsq + 64;          // 64
    int* lis = (int*)(ksq + 64);    // 64
    int* yb  = lis + 64;            // 64

    int tid = threadIdx.x;
    int bbase = blockIdx.x * 64;
    int split = blockIdx.y;
    int br = blockIdx.z;
    const float* feats = br ? f2 : f1;
    const int* lidx = br ? li2 : li1;
    const float* ldist = br ? ld2 : ld1;
    const float* xt = br ? g_xt2 : g_xt1;
    const int* yi = br ? g_yidx2 : g_yidx1;

    load64(Qs, qsq, xt + (size_t)bbase * ND, 64, tid);
    if (tid < 64) yb[tid] = yi[bbase + tid];
    __syncthreads();
    for (int i = tid; i < NL * 64; i += 256) {
        int l = i >> 6, bl = i & 63;
        Gt[l * 65 + bl] = FETA * __ldg(&ldist[l * NL + yb[bl]]);
    }

    int w = tid >> 5, lane = tid & 31;
    int lr = lane >> 2, lc = lane & 3;
    int m0 = (w & 3) * 16;
    int bq = (w >> 2) * 32;
    const uint32_t* Ku = (const uint32_t*)Ks;
    const uint32_t* Qu = (const uint32_t*)Qs;

    int txb = tid & 15, tyb = tid >> 4;   // phase B: b = txb*4+i, dy = tyb*2+j
    float accn[4][2] = {};
    float den[4] = {};

    int c0 = split * CHP2, c1 = min(c0 + CHP2, CHT);
    for (int c = c0; c < c1; ++c) {
        int n0 = c * 64;
        int cnt = min(64, NN - n0);
        __syncthreads();
        load64(Ks, ksq, feats + (size_t)n0 * ND, cnt, tid);
        {   // star_labels chunk [cnt, 32] -> Vs
            const float4* s4 = (const float4*)(sl + (size_t)n0 * NDY);
#pragma unroll
            for (int it = 0; it < 2; ++it) {
                int f = tid + it * 256;
                int r = f >> 3, kq = f & 7;
                float4 v = make_float4(0.f, 0.f, 0.f, 0.f);
                if (r < cnt) v = s4[r * 8 + kq];
                *(float4*)(Vs + r * 32 + kq * 4) = v;
            }
        }
        if (tid < 64) lis[tid] = (n0 + tid < NN) ? lidx[n0 + tid] : 0;
        __syncthreads();

        // ---- phase A: E2 = exp(-(max(d,0) + eta*ldist)) via tf32 mma ----
        float cfr[4][4];
#pragma unroll
        for (int t = 0; t < 4; ++t)
#pragma unroll
            for (int rg = 0; rg < 4; ++rg) cfr[t][rg] = 0.f;
#pragma unroll
        for (int ks = 0; ks < 64; ks += 8) {
            uint32_t a0 = Ku[(m0 + lr) * 68 + ks + lc];
            uint32_t a1 = Ku[(m0 + 8 + lr) * 68 + ks + lc];
            uint32_t a2 = Ku[(m0 + lr) * 68 + ks + 4 + lc];
            uint32_t a3 = Ku[(m0 + 8 + lr) * 68 + ks + 4 + lc];
#pragma unroll
            for (int t = 0; t < 4; ++t) {
                int bt = bq + t * 8;
                uint32_t b0 = Qu[(bt + lr) * 68 + ks + lc];
                uint32_t b1 = Qu[(bt + lr) * 68 + ks + 4 + lc];
                mma_tf32(cfr[t], a0, a1, a2, a3, b0, b1);
            }
        }
#pragma unroll
        for (int t = 0; t < 4; ++t) {
            int bt = bq + t * 8;
#pragma unroll
            for (int rg = 0; rg < 4; ++rg) {
                int nl = m0 + lr + ((rg >> 1) ? 8 : 0);
                int bl = bt + 2 * lc + (rg & 1);
                int ng = n0 + nl;
                float d = fmaxf(qsq[bl] + ksq[nl] - 2.f * cfr[t][rg], 0.f);
                float ev = (ng < NN) ? __expf(-(d + Gt[lis[nl] * 65 + bl])) : 0.f;
                Es[nl * 68 + bl] = ev;
            }
        }
        __syncthreads();

        // ---- phase B: num[b,dy] += e2[n,b] * V[n,dy]; den[b] += e2[n,b] ----
#pragma unroll 4
        for (int n = 0; n < 64; ++n) {
            float4 er = *(float4*)(Es + n * 68 + txb * 4);
            float2 vv = *(float2*)(Vs + n * 32 + tyb * 2);
            float er4[4] = {er.x, er.y, er.z, er.w};
#pragma unroll
            for (int i = 0; i < 4; ++i) {
                accn[i][0] += er4[i] * vv.x;
                accn[i][1] += er4[i] * vv.y;
            }
            if (tyb == 0) {
#pragma unroll
                for (int i = 0; i < 4; ++i) den[i] += er4[i];
            }
        }
    }

    float* pnum = g_pnum + ((size_t)br * NS2 + split) * NB * NDY;
    float* pden = g_pden + ((size_t)br * NS2 + split) * NB;
#pragma unroll
    for (int i = 0; i < 4; ++i)
        *(float2*)&pnum[(bbase + txb * 4 + i) * NDY + tyb * 2] =
            make_float2(accn[i][0], accn[i][1]);
    if (tyb == 0) {
#pragma unroll
        for (int i = 0; i < 4; ++i) pden[bbase + txb * 4 + i] = den[i];
    }
}

__global__ void k_final(float* __restrict__ out) {
    int i = blockIdx.x * 256 + threadIdx.x;
    if (i >= NB * NDY) return;
    int b = i / NDY;
    float n1 = 0.f, n2 = 0.f, d1 = 0.f, d2 = 0.f;
#pragma unroll
    for (int t = 0; t < NS2; ++t) {
        n1 += g_pnum[(size_t)t * NB * NDY + i];
        n2 += g_pnum[((size_t)NS2 + t) * NB * NDY + i];
        d1 += g_pden[t * NB + b];
        d2 += g_pden[(NS2 + t) * NB + b];
    }
    out[i] = 0.5f * (n1 / d1 + n2 / d2);
}

#define SMEM1 ((4352 * 5 + 128) * 4)                              // 87552 B
#define SMEM2 ((4352 * 3 + 2048 + 6500 + 128 + 128) * 4)          // 87440 B

extern "C" void kernel_launch(void* const* d_in, const int* in_sizes, int n_in,
                              void* d_out, int out_size) {
    const float* x   = (const float*)d_in[0];
    const float* sf  = (const float*)d_in[1];
    const float* sl  = (const float*)d_in[2];
    const float* f1  = (const float*)d_in[3];
    const float* f2  = (const float*)d_in[4];
    const float* u1  = (const float*)d_in[5];
    const float* u2  = (const float*)d_in[6];
    const float* ld1 = (const float*)d_in[7];
    const float* ld2 = (const float*)d_in[8];
    const float* W1  = (const float*)d_in[9];
    const float* b1  = (const float*)d_in[10];
    const float* W2  = (const float*)d_in[11];
    const float* b2  = (const float*)d_in[12];
    const int*   li1 = (const int*)d_in[13];
    const int*   li2 = (const int*)d_in[14];
    float* out = (float*)d_out;

    cudaFuncSetAttribute(k_pass1, cudaFuncAttributeMaxDynamicSharedMemorySize, SMEM1);
    cudaFuncSetAttribute(k_pass2, cudaFuncAttributeMaxDynamicSharedMemorySize, SMEM2);

    k_init<<<8, 256>>>();
    k_pass1<<<dim3(32, NS1), 256, SMEM1>>>(x, sf, f1, f2);
    k_mid<<<256, 256>>>(f1, f2, W1, b1, W2, b2, u1, u2);
    k_pass2<<<dim3(32, NS2, 2), 256, SMEM2>>>(f1, f2, sl, li1, li2, ld1, ld2);
    k_final<<<256, 256>>>(out);
}